// round 9
// baseline (speedup 1.0000x reference)
#include <cuda_runtime.h>
#include <math.h>

// Problem constants
#define BATCH   8
#define SEQ     4096
#define M_TOTAL (BATCH * SEQ)   // 32768
#define NCODES  1024
#define KDIM    256
#define TOPM    3

// GEMM tiling
#define BM 128
#define BN 128
#define BK 16

// ---------------------------------------------------------------------------
// Packed fp32x2 helpers (sm_100 Blackwell dual-lane FP32, bit-exact vs fmaf)
// ---------------------------------------------------------------------------
__device__ __forceinline__ unsigned long long pack2(float x) {
    unsigned long long r;
    asm("mov.b64 %0, {%1, %1};" : "=l"(r) : "f"(x));
    return r;
}
__device__ __forceinline__ void fma2(unsigned long long& acc,
                                     unsigned long long a,
                                     unsigned long long b) {
    asm("fma.rn.f32x2 %0, %1, %2, %0;" : "+l"(acc) : "l"(a), "l"(b));
}
__device__ __forceinline__ float2 unpack2(unsigned long long v) {
    float2 f;
    asm("mov.b64 {%0, %1}, %2;" : "=f"(f.x), "=f"(f.y) : "l"(v));
    return f;
}

// ---------------------------------------------------------------------------
// Kernel 1: sim = q @ codes^T   (M=32768, N=1024, K=256), fp32 via fma.f32x2
// UNCHANGED from the 367.7us best: at the FFMA2 RF-banking roofline.
// ---------------------------------------------------------------------------
__global__ __launch_bounds__(256, 2)
void vq_sgemm_kernel(const float* __restrict__ A,    // [M_TOTAL, KDIM]
                     const float* __restrict__ Bm,   // [NCODES,  KDIM]
                     float* __restrict__ C)          // [M_TOTAL, NCODES]
{
    __shared__ float As[BK][BM + 4];   // stride 132 floats
    __shared__ float Bs[BK][BN + 4];

    const int bn0 = blockIdx.x * BN;
    const int bm0 = blockIdx.y * BM;
    const int tid = threadIdx.x;
    const int tx  = tid & 15;          // 0..15 -> N
    const int ty  = tid >> 4;          // 0..15 -> M

    const int lrow0 = tid >> 2;              // 0..63
    const int lrow1 = lrow0 + 64;            // 64..127
    const int lc4   = (tid & 3) * 4;         // 0,4,8,12

    const float* Aptr0 = &A[(size_t)(bm0 + lrow0) * KDIM + lc4];
    const float* Aptr1 = &A[(size_t)(bm0 + lrow1) * KDIM + lc4];
    const float* Bptr0 = &Bm[(size_t)(bn0 + lrow0) * KDIM + lc4];
    const float* Bptr1 = &Bm[(size_t)(bn0 + lrow1) * KDIM + lc4];

    unsigned long long acc2[8][4];
#pragma unroll
    for (int i = 0; i < 8; i++)
#pragma unroll
        for (int j = 0; j < 4; j++) acc2[i][j] = 0ull;

    // Prologue: load chunk 0
    float4 pa0 = *reinterpret_cast<const float4*>(Aptr0);
    float4 pa1 = *reinterpret_cast<const float4*>(Aptr1);
    float4 pb0 = *reinterpret_cast<const float4*>(Bptr0);
    float4 pb1 = *reinterpret_cast<const float4*>(Bptr1);

#pragma unroll 1
    for (int c = 0; c < KDIM / BK; c++) {
        As[lc4 + 0][lrow0] = pa0.x; As[lc4 + 1][lrow0] = pa0.y;
        As[lc4 + 2][lrow0] = pa0.z; As[lc4 + 3][lrow0] = pa0.w;
        As[lc4 + 0][lrow1] = pa1.x; As[lc4 + 1][lrow1] = pa1.y;
        As[lc4 + 2][lrow1] = pa1.z; As[lc4 + 3][lrow1] = pa1.w;
        Bs[lc4 + 0][lrow0] = pb0.x; Bs[lc4 + 1][lrow0] = pb0.y;
        Bs[lc4 + 2][lrow0] = pb0.z; Bs[lc4 + 3][lrow0] = pb0.w;
        Bs[lc4 + 0][lrow1] = pb1.x; Bs[lc4 + 1][lrow1] = pb1.y;
        Bs[lc4 + 2][lrow1] = pb1.z; Bs[lc4 + 3][lrow1] = pb1.w;
        __syncthreads();

        if (c + 1 < KDIM / BK) {
            int koff = (c + 1) * BK;
            pa0 = *reinterpret_cast<const float4*>(Aptr0 + koff);
            pa1 = *reinterpret_cast<const float4*>(Aptr1 + koff);
            pb0 = *reinterpret_cast<const float4*>(Bptr0 + koff);
            pb1 = *reinterpret_cast<const float4*>(Bptr1 + koff);
        }

#pragma unroll
        for (int kk = 0; kk < BK; kk++) {
            float4 a0 = *reinterpret_cast<const float4*>(&As[kk][ty * 4]);
            float4 a1 = *reinterpret_cast<const float4*>(&As[kk][64 + ty * 4]);
            ulonglong2 bp = *reinterpret_cast<const ulonglong2*>(&Bs[kk][tx * 4]);
            ulonglong2 bq = *reinterpret_cast<const ulonglong2*>(&Bs[kk][64 + tx * 4]);

            float av[8] = {a0.x, a0.y, a0.z, a0.w, a1.x, a1.y, a1.z, a1.w};
#pragma unroll
            for (int i = 0; i < 8; i++) {
                unsigned long long ap = pack2(av[i]);
                fma2(acc2[i][0], ap, bp.x);
                fma2(acc2[i][1], ap, bp.y);
                fma2(acc2[i][2], ap, bq.x);
                fma2(acc2[i][3], ap, bq.y);
            }
        }
        __syncthreads();
    }

#pragma unroll
    for (int ih = 0; ih < 2; ih++) {
#pragma unroll
        for (int ii = 0; ii < 4; ii++) {
            int i = ih * 4 + ii;
            int row = bm0 + ih * 64 + ty * 4 + ii;
            float* crow = &C[(size_t)row * NCODES + bn0];
            float2 c0 = unpack2(acc2[i][0]);
            float2 c1 = unpack2(acc2[i][1]);
            float2 c2 = unpack2(acc2[i][2]);
            float2 c3 = unpack2(acc2[i][3]);
            *reinterpret_cast<float4*>(&crow[tx * 4]) =
                make_float4(c0.x, c0.y, c1.x, c1.y);
            *reinterpret_cast<float4*>(&crow[64 + tx * 4]) =
                make_float4(c2.x, c2.y, c3.x, c3.y);
        }
    }
}

// ---------------------------------------------------------------------------
// Kernel 2: per-row masked top-3 + Gumbel softmax. One warp per row.
// Warp-UNIFORM quad gate via __any_sync: a real (non-if-convertible) branch
// skips the insert chain when no lane's quad can improve its top-3.
// Rows processed in reverse so recently written GEMM tiles hit in L2.
// ---------------------------------------------------------------------------
__global__ __launch_bounds__(256)
void vq_topk_kernel(const float* __restrict__ sim,   // [M_TOTAL, NCODES]
                    const int*   __restrict__ mask,  // [M_TOTAL]
                    const float* __restrict__ u,     // [M_TOTAL, 3]
                    float* __restrict__ out_idx,     // [M_TOTAL, 3] (as float)
                    float* __restrict__ out_w)       // [M_TOTAL, 3]
{
    const int row  = (M_TOTAL - 1) - (blockIdx.x * 8 + (threadIdx.x >> 5));
    const int lane = threadIdx.x & 31;
    const float* srow = sim + (size_t)row * NCODES;

    const float NEG_INF = -__int_as_float(0x7f800000);  // -inf
    float v0 = NEG_INF, v1 = NEG_INF, v2 = NEG_INF;
    int   i0 = 0x7fffffff, i1 = 0x7fffffff, i2 = 0x7fffffff;

    // Within-lane index order is strictly increasing, so strict '>' keeps the
    // smaller index on ties; gating on quad-max <= v2 is tiebreak-safe.
#pragma unroll 1
    for (int t = 0; t < NCODES / 128; t++) {
        int base = t * 128 + lane * 4;
        float4 v4 = *reinterpret_cast<const float4*>(&srow[base]);
        float m = fmaxf(fmaxf(v4.x, v4.y), fmaxf(v4.z, v4.w));
        // Warp-uniform gate: cannot be if-converted; skips chain when no lane
        // in the warp can improve its local top-3 with this quad.
        if (__any_sync(0xffffffffu, m > v2)) {
            float vv[4] = {v4.x, v4.y, v4.z, v4.w};
#pragma unroll
            for (int e = 0; e < 4; e++) {
                float v = vv[e];
                int idx = base + e;
                // Branchless insert (nested selects) to avoid intra-body
                // divergence; validated case-by-case:
                bool g0 = v > v0, g1 = v > v1, g2 = v > v2;
                float nv2 = g1 ? v1 : (g2 ? v : v2);
                int   ni2 = g1 ? i1 : (g2 ? idx : i2);
                float nv1 = g0 ? v0 : (g1 ? v : v1);
                int   ni1 = g0 ? i0 : (g1 ? idx : i1);
                float nv0 = g0 ? v : v0;
                int   ni0 = g0 ? idx : i0;
                v0 = nv0; v1 = nv1; v2 = nv2;
                i0 = ni0; i1 = ni1; i2 = ni2;
            }
        }
    }

    // Warp merge: 3 rounds of (value, index) arg-max with smaller-index
    // tie-break. Each lane keeps a cursor into its sorted local top-3.
    float lv[3] = {v0, v1, v2};
    int   li[3] = {i0, i1, i2};
    float tv[3];
    int   ti[3];
    int p = 0;
#pragma unroll
    for (int rr = 0; rr < 3; rr++) {
        float bv = (p < 3) ? lv[p] : NEG_INF;
        int   bi = (p < 3) ? li[p] : 0x7fffffff;
#pragma unroll
        for (int off = 16; off > 0; off >>= 1) {
            float ov = __shfl_xor_sync(0xffffffffu, bv, off);
            int   oi = __shfl_xor_sync(0xffffffffu, bi, off);
            if (ov > bv || (ov == bv && oi < bi)) { bv = ov; bi = oi; }
        }
        tv[rr] = bv; ti[rr] = bi;
        if (p < 3 && li[p] == bi) p++;   // winner lane advances its cursor
    }

    if (lane == 0) {
        int m = mask[row];
        if (m == 0) {
            // All sims masked to -10000 (equal): lax.top_k -> indices 0,1,2;
            // weights zeroed by the mask.
#pragma unroll
            for (int rr = 0; rr < 3; rr++) {
                out_idx[row * 3 + rr] = (float)rr;
                out_w[row * 3 + rr]   = 0.0f;
            }
        } else {
            float l[3];
#pragma unroll
            for (int rr = 0; rr < 3; rr++) {
                float uu = u[row * 3 + rr];
                uu = fminf(fmaxf(uu, 1e-7f), 1.0f - 1e-7f);
                float inner = fmaxf(-logf(uu), 1e-7f);
                float g = -logf(inner);
                l[rr] = tv[rr] + g;          // TAU = 1.0
            }
            float mx = fmaxf(l[0], fmaxf(l[1], l[2]));
            float e0 = expf(l[0] - mx);
            float e1 = expf(l[1] - mx);
            float e2 = expf(l[2] - mx);
            float inv = 1.0f / (e0 + e1 + e2);
#pragma unroll
            for (int rr = 0; rr < 3; rr++) {
                out_idx[row * 3 + rr] = (float)ti[rr];
            }
            out_w[row * 3 + 0] = e0 * inv;
            out_w[row * 3 + 1] = e1 * inv;
            out_w[row * 3 + 2] = e2 * inv;
        }
    }
}

// ---------------------------------------------------------------------------
// Launch: d_out layout = [top_idx (B*N*3) | weights (B*N*3) | sim (B*N*K)]
// ---------------------------------------------------------------------------
extern "C" void kernel_launch(void* const* d_in, const int* in_sizes, int n_in,
                              void* d_out, int out_size)
{
    const float* q     = (const float*)d_in[0];   // [8,4096,256]
    const float* codes = (const float*)d_in[1];   // [1024,256]
    const int*   mask  = (const int*)  d_in[2];   // [8,4096]
    const float* u     = (const float*)d_in[3];   // [8,4096,3]

    float* out      = (float*)d_out;
    float* out_idx  = out;
    float* out_w    = out + (size_t)M_TOTAL * TOPM;
    float* sim      = out + (size_t)2 * M_TOTAL * TOPM;

    dim3 grid(NCODES / BN, M_TOTAL / BM);
    vq_sgemm_kernel<<<grid, 256>>>(q, codes, sim);

    vq_topk_kernel<<<M_TOTAL / 8, 256>>>(sim, mask, u, out_idx, out_w);
}

// round 11
// speedup vs baseline: 1.0520x; 1.0520x over previous
#include <cuda_runtime.h>
#include <math.h>

// Problem constants
#define BATCH   8
#define SEQ     4096
#define M_TOTAL (BATCH * SEQ)   // 32768
#define NCODES  1024
#define KDIM    256
#define TOPM    3

// GEMM tiling
#define BM 128
#define BN 128
#define BK 16
#define NTILES (NCODES / BN)    // 8

// Per-(row, n-tile) max of sim: 32768 x 8 floats = 1 MB scratch
__device__ float g_rowmax[(size_t)M_TOTAL * NTILES];

// ---------------------------------------------------------------------------
// Packed fp32x2 helpers (sm_100 Blackwell dual-lane FP32, bit-exact vs fmaf)
// ---------------------------------------------------------------------------
__device__ __forceinline__ unsigned long long pack2(float x) {
    unsigned long long r;
    asm("mov.b64 %0, {%1, %1};" : "=l"(r) : "f"(x));
    return r;
}
__device__ __forceinline__ void fma2(unsigned long long& acc,
                                     unsigned long long a,
                                     unsigned long long b) {
    asm("fma.rn.f32x2 %0, %1, %2, %0;" : "+l"(acc) : "l"(a), "l"(b));
}
__device__ __forceinline__ float2 unpack2(unsigned long long v) {
    float2 f;
    asm("mov.b64 {%0, %1}, %2;" : "=f"(f.x), "=f"(f.y) : "l"(v));
    return f;
}

// ---------------------------------------------------------------------------
// Kernel 1: sim = q @ codes^T via fma.f32x2 (at the FFMA2 RF-banking roofline)
// Epilogue additionally emits per-(row, tile) max for the topk prefilter:
// 16 fmax/shfl ops per row (~130 ops/thread) -- deliberately tiny, unlike the
// R6 fused-top3 epilogue that cost +85us.
// ---------------------------------------------------------------------------
__global__ __launch_bounds__(256, 2)
void vq_sgemm_kernel(const float* __restrict__ A,    // [M_TOTAL, KDIM]
                     const float* __restrict__ Bm,   // [NCODES,  KDIM]
                     float* __restrict__ C)          // [M_TOTAL, NCODES]
{
    __shared__ float As[BK][BM + 4];   // stride 132 floats
    __shared__ float Bs[BK][BN + 4];

    const int bn0 = blockIdx.x * BN;
    const int bm0 = blockIdx.y * BM;
    const int tid = threadIdx.x;
    const int tx  = tid & 15;          // 0..15 -> N
    const int ty  = tid >> 4;          // 0..15 -> M

    const int lrow0 = tid >> 2;              // 0..63
    const int lrow1 = lrow0 + 64;            // 64..127
    const int lc4   = (tid & 3) * 4;         // 0,4,8,12

    const float* Aptr0 = &A[(size_t)(bm0 + lrow0) * KDIM + lc4];
    const float* Aptr1 = &A[(size_t)(bm0 + lrow1) * KDIM + lc4];
    const float* Bptr0 = &Bm[(size_t)(bn0 + lrow0) * KDIM + lc4];
    const float* Bptr1 = &Bm[(size_t)(bn0 + lrow1) * KDIM + lc4];

    unsigned long long acc2[8][4];
#pragma unroll
    for (int i = 0; i < 8; i++)
#pragma unroll
        for (int j = 0; j < 4; j++) acc2[i][j] = 0ull;

    // Prologue: load chunk 0
    float4 pa0 = *reinterpret_cast<const float4*>(Aptr0);
    float4 pa1 = *reinterpret_cast<const float4*>(Aptr1);
    float4 pb0 = *reinterpret_cast<const float4*>(Bptr0);
    float4 pb1 = *reinterpret_cast<const float4*>(Bptr1);

#pragma unroll 1
    for (int c = 0; c < KDIM / BK; c++) {
        As[lc4 + 0][lrow0] = pa0.x; As[lc4 + 1][lrow0] = pa0.y;
        As[lc4 + 2][lrow0] = pa0.z; As[lc4 + 3][lrow0] = pa0.w;
        As[lc4 + 0][lrow1] = pa1.x; As[lc4 + 1][lrow1] = pa1.y;
        As[lc4 + 2][lrow1] = pa1.z; As[lc4 + 3][lrow1] = pa1.w;
        Bs[lc4 + 0][lrow0] = pb0.x; Bs[lc4 + 1][lrow0] = pb0.y;
        Bs[lc4 + 2][lrow0] = pb0.z; Bs[lc4 + 3][lrow0] = pb0.w;
        Bs[lc4 + 0][lrow1] = pb1.x; Bs[lc4 + 1][lrow1] = pb1.y;
        Bs[lc4 + 2][lrow1] = pb1.z; Bs[lc4 + 3][lrow1] = pb1.w;
        __syncthreads();

        if (c + 1 < KDIM / BK) {
            int koff = (c + 1) * BK;
            pa0 = *reinterpret_cast<const float4*>(Aptr0 + koff);
            pa1 = *reinterpret_cast<const float4*>(Aptr1 + koff);
            pb0 = *reinterpret_cast<const float4*>(Bptr0 + koff);
            pb1 = *reinterpret_cast<const float4*>(Bptr1 + koff);
        }

#pragma unroll
        for (int kk = 0; kk < BK; kk++) {
            float4 a0 = *reinterpret_cast<const float4*>(&As[kk][ty * 4]);
            float4 a1 = *reinterpret_cast<const float4*>(&As[kk][64 + ty * 4]);
            ulonglong2 bp = *reinterpret_cast<const ulonglong2*>(&Bs[kk][tx * 4]);
            ulonglong2 bq = *reinterpret_cast<const ulonglong2*>(&Bs[kk][64 + tx * 4]);

            float av[8] = {a0.x, a0.y, a0.z, a0.w, a1.x, a1.y, a1.z, a1.w};
#pragma unroll
            for (int i = 0; i < 8; i++) {
                unsigned long long ap = pack2(av[i]);
                fma2(acc2[i][0], ap, bp.x);
                fma2(acc2[i][1], ap, bp.y);
                fma2(acc2[i][2], ap, bq.x);
                fma2(acc2[i][3], ap, bq.y);
            }
        }
        __syncthreads();
    }

#pragma unroll
    for (int ih = 0; ih < 2; ih++) {
#pragma unroll
        for (int ii = 0; ii < 4; ii++) {
            int i = ih * 4 + ii;
            int row = bm0 + ih * 64 + ty * 4 + ii;
            float* crow = &C[(size_t)row * NCODES + bn0];
            float2 c0 = unpack2(acc2[i][0]);
            float2 c1 = unpack2(acc2[i][1]);
            float2 c2 = unpack2(acc2[i][2]);
            float2 c3 = unpack2(acc2[i][3]);
            *reinterpret_cast<float4*>(&crow[tx * 4]) =
                make_float4(c0.x, c0.y, c1.x, c1.y);
            *reinterpret_cast<float4*>(&crow[64 + tx * 4]) =
                make_float4(c2.x, c2.y, c3.x, c3.y);

            // Row-tile max for the topk prefilter. Lanes [0..15] / [16..31]
            // hold two distinct rows; xor 1,2,4,8 stays within each group.
            float mrow = fmaxf(fmaxf(fmaxf(c0.x, c0.y), fmaxf(c1.x, c1.y)),
                               fmaxf(fmaxf(c2.x, c2.y), fmaxf(c3.x, c3.y)));
#pragma unroll
            for (int off = 1; off <= 8; off <<= 1)
                mrow = fmaxf(mrow, __shfl_xor_sync(0xffffffffu, mrow, off));
            if (tx == 0)
                g_rowmax[(size_t)row * NTILES + blockIdx.x] = mrow;
        }
    }
}

// ---------------------------------------------------------------------------
// Kernel 2: per-row masked top-3 + Gumbel softmax. One warp per row.
// Tile-max prefilter: only tiles whose max ranks in the top-3 of the row's
// 8 tile-maxes can contain top-3 elements (a tile with >=3 strictly greater
// tile-maxes has all elements < final v2; ties kept conservatively).
// keep-mask is warp-uniform -> real branch, whole 512B tile loads skipped.
// ---------------------------------------------------------------------------
__global__ __launch_bounds__(256)
void vq_topk_kernel(const float* __restrict__ sim,   // [M_TOTAL, NCODES]
                    const int*   __restrict__ mask,  // [M_TOTAL]
                    const float* __restrict__ u,     // [M_TOTAL, 3]
                    float* __restrict__ out_idx,     // [M_TOTAL, 3] (as float)
                    float* __restrict__ out_w)       // [M_TOTAL, 3]
{
    const int row  = blockIdx.x * 8 + (threadIdx.x >> 5);
    const int lane = threadIdx.x & 31;
    const float* srow = sim + (size_t)row * NCODES;

    // --- Tile selection from rowmax ---
    float x = g_rowmax[(size_t)row * NTILES + (lane & 7)];
    int cnt = 0;
#pragma unroll
    for (int j = 0; j < 8; j++) {
        float xj = __shfl_sync(0xffffffffu, x, j);
        cnt += (xj > x) ? 1 : 0;
    }
    unsigned keep = __ballot_sync(0xffffffffu, cnt <= 2) & 0xffu;  // bits 0..7

    const float NEG_INF = -__int_as_float(0x7f800000);  // -inf
    float v0 = NEG_INF, v1 = NEG_INF, v2 = NEG_INF;
    int   i0 = 0x7fffffff, i1 = 0x7fffffff, i2 = 0x7fffffff;

    // Within-lane index order is strictly increasing inside each tile, and
    // tiles are visited in ascending order, so strict '>' keeps the smaller
    // index on ties.
#pragma unroll
    for (int t = 0; t < NTILES; t++) {
        if (keep & (1u << t)) {    // warp-uniform branch
            int base = t * 128 + lane * 4;
            float4 v4 = *reinterpret_cast<const float4*>(&srow[base]);
            float vv[4] = {v4.x, v4.y, v4.z, v4.w};
#pragma unroll
            for (int e = 0; e < 4; e++) {
                float v = vv[e];
                int idx = base + e;
                if (v > v0)      { v2 = v1; i2 = i1; v1 = v0; i1 = i0; v0 = v; i0 = idx; }
                else if (v > v1) { v2 = v1; i2 = i1; v1 = v;  i1 = idx; }
                else if (v > v2) { v2 = v;  i2 = idx; }
            }
        }
    }

    // Warp merge: 3 rounds of (value, index) arg-max with smaller-index
    // tie-break. Each lane keeps a cursor into its sorted local top-3.
    float lv[3] = {v0, v1, v2};
    int   li[3] = {i0, i1, i2};
    float tv[3];
    int   ti[3];
    int p = 0;
#pragma unroll
    for (int rr = 0; rr < 3; rr++) {
        float bv = (p < 3) ? lv[p] : NEG_INF;
        int   bi = (p < 3) ? li[p] : 0x7fffffff;
#pragma unroll
        for (int off = 16; off > 0; off >>= 1) {
            float ov = __shfl_xor_sync(0xffffffffu, bv, off);
            int   oi = __shfl_xor_sync(0xffffffffu, bi, off);
            if (ov > bv || (ov == bv && oi < bi)) { bv = ov; bi = oi; }
        }
        tv[rr] = bv; ti[rr] = bi;
        if (p < 3 && li[p] == bi) p++;   // winner lane advances its cursor
    }

    if (lane == 0) {
        int m = mask[row];
        if (m == 0) {
            // All sims masked to -10000 (equal): lax.top_k -> indices 0,1,2;
            // weights zeroed by the mask.
#pragma unroll
            for (int rr = 0; rr < 3; rr++) {
                out_idx[row * 3 + rr] = (float)rr;
                out_w[row * 3 + rr]   = 0.0f;
            }
        } else {
            float l[3];
#pragma unroll
            for (int rr = 0; rr < 3; rr++) {
                float uu = u[row * 3 + rr];
                uu = fminf(fmaxf(uu, 1e-7f), 1.0f - 1e-7f);
                float inner = fmaxf(-logf(uu), 1e-7f);
                float g = -logf(inner);
                l[rr] = tv[rr] + g;          // TAU = 1.0
            }
            float mx = fmaxf(l[0], fmaxf(l[1], l[2]));
            float e0 = expf(l[0] - mx);
            float e1 = expf(l[1] - mx);
            float e2 = expf(l[2] - mx);
            float inv = 1.0f / (e0 + e1 + e2);
#pragma unroll
            for (int rr = 0; rr < 3; rr++) {
                out_idx[row * 3 + rr] = (float)ti[rr];
            }
            out_w[row * 3 + 0] = e0 * inv;
            out_w[row * 3 + 1] = e1 * inv;
            out_w[row * 3 + 2] = e2 * inv;
        }
    }
}

// ---------------------------------------------------------------------------
// Launch: d_out layout = [top_idx (B*N*3) | weights (B*N*3) | sim (B*N*K)]
// ---------------------------------------------------------------------------
extern "C" void kernel_launch(void* const* d_in, const int* in_sizes, int n_in,
                              void* d_out, int out_size)
{
    const float* q     = (const float*)d_in[0];   // [8,4096,256]
    const float* codes = (const float*)d_in[1];   // [1024,256]
    const int*   mask  = (const int*)  d_in[2];   // [8,4096]
    const float* u     = (const float*)d_in[3];   // [8,4096,3]

    float* out      = (float*)d_out;
    float* out_idx  = out;
    float* out_w    = out + (size_t)M_TOTAL * TOPM;
    float* sim      = out + (size_t)2 * M_TOTAL * TOPM;

    dim3 grid(NCODES / BN, M_TOTAL / BM);
    vq_sgemm_kernel<<<grid, 256>>>(q, codes, sim);

    vq_topk_kernel<<<M_TOTAL / 8, 256>>>(sim, mask, u, out_idx, out_w);
}